// round 7
// baseline (speedup 1.0000x reference)
#include <cuda_runtime.h>

// Problem constants (fixed by the dataset)
#define DFEAT   128     // node / edge feature dim
#define DHID    256     // hidden dim
#define KIN     256     // 2*DFEAT, GEMM1 K
#define TILE_M  64      // nodes per block in MLP kernel
#define KT      16      // K-tile depth
#define MAXN    50000

// Scratch: aggregated edge features per node. 50000*128*4 = 25.6 MB.
// 16B alignment required for red.global.add.v4.f32.
__device__ __align__(16) float g_agg[(size_t)MAXN * DFEAT];
__device__ int g_is64;   // 1 if edge_index is int64 on device, 0 if int32

// ---------------------------------------------------------------------------
// Kernel 0: detect edge_index dtype. int64 little-endian data with values
// < 50000 looks like [val,0,val,0,...] when viewed as int32. Genuine int32
// data has random node ids in the odd slots (P(all 1024 zero) ~ 0).
// Reads only the first 2048 int32 words — safe under either dtype.
// ---------------------------------------------------------------------------
__global__ void detect_kernel(const int* __restrict__ ei32)
{
    __shared__ int s_ok;
    if (threadIdx.x == 0) s_ok = 1;
    __syncthreads();
    int bad = 0;
    for (int i = threadIdx.x; i < 1024; i += 256)
        if (ei32[2 * i + 1] != 0) bad = 1;
    if (bad) atomicAnd(&s_ok, 0);
    __syncthreads();
    if (threadIdx.x == 0) g_is64 = s_ok;
}

// ---------------------------------------------------------------------------
// Kernel 1: zero the aggregation buffer
// ---------------------------------------------------------------------------
__global__ void zero_kernel(int n4)
{
    int i = blockIdx.x * blockDim.x + threadIdx.x;
    if (i < n4) ((float4*)g_agg)[i] = make_float4(0.f, 0.f, 0.f, 0.f);
}

// ---------------------------------------------------------------------------
// Kernel 2: scatter-add edge features onto destination nodes.
// One warp per edge; lane l handles floats [4l, 4l+4). Uses vector RED
// (red.global.add.v4.f32, sm_90+) to quarter the atomic instruction count.
// ---------------------------------------------------------------------------
__global__ void scatter_kernel(const float* __restrict__ edge_attr,
                               const void* __restrict__ edge_index,
                               int E)
{
    int w    = (blockIdx.x * blockDim.x + threadIdx.x) >> 5;
    int lane = threadIdx.x & 31;
    if (w >= E) return;

    int dst;
    if (g_is64)
        dst = (int)((const long long*)edge_index)[(size_t)E + w];  // row 1
    else
        dst = ((const int*)edge_index)[(size_t)E + w];
    dst = min(max(dst, 0), MAXN - 1);   // identity on valid data

    float4 v = ((const float4*)edge_attr)[(size_t)w * 32 + lane];
    float* p = g_agg + (size_t)dst * DFEAT + lane * 4;
    asm volatile("red.global.add.v4.f32 [%0], {%1, %2, %3, %4};"
                 :: "l"(p), "f"(v.x), "f"(v.y), "f"(v.z), "f"(v.w)
                 : "memory");
}

// ---------------------------------------------------------------------------
// Kernel 3: fused MLP + LayerNorm + residual.
// Block = 256 threads (16x16), handles TILE_M=64 nodes.
//   A  = [x | agg] staged TRANSPOSED in smem: At[k][m]   (conflict-free LDS.128)
//   H1 = silu(A @ W1 + b1) staged transposed: H1t[k][m]
//   H2 = H1 @ W2 + b2  -> LN -> + x -> out
// W tiles (16 x N) double-buffered in smem, LDG prefetch into registers.
// ---------------------------------------------------------------------------
__global__ __launch_bounds__(256, 1)
void mlp_kernel(const float* __restrict__ x,
                const float* __restrict__ W1, const float* __restrict__ b1,
                const float* __restrict__ W2, const float* __restrict__ b2,
                const float* __restrict__ gamma, const float* __restrict__ beta,
                float* __restrict__ out, int n)
{
    extern __shared__ float sm[];
    float* At  = sm;                        // [KIN][TILE_M]   = 16384 f
    float* H1t = sm + KIN * TILE_M;         // [DHID][TILE_M]  = 16384 f
    float* Wsh = sm + 2 * KIN * TILE_M;     // 2 x [KT][DHID]  =  8192 f

    const int tid = threadIdx.x;
    const int tx  = tid & 15;
    const int ty  = tid >> 4;
    const int m0  = blockIdx.x * TILE_M;

    // ---- stage A = [x | agg] transposed --------------------------------
    for (int u = tid; u < TILE_M * (KIN / 4); u += 256) {
        int m  = u >> 6;            // u / 64
        int c4 = u & 63;
        int k  = c4 * 4;
        int node = m0 + m;
        float4 v = make_float4(0.f, 0.f, 0.f, 0.f);
        if (node < n) {
            const float* src = (k < DFEAT)
                ? (x     + (size_t)node * DFEAT + k)
                : (g_agg + (size_t)node * DFEAT + (k - DFEAT));
            v = *(const float4*)src;
        }
        At[(k + 0) * TILE_M + m] = v.x;
        At[(k + 1) * TILE_M + m] = v.y;
        At[(k + 2) * TILE_M + m] = v.z;
        At[(k + 3) * TILE_M + m] = v.w;
    }
    __syncthreads();

    // ---- GEMM1: H1 = silu(A @ W1 + b1) ---------------------------------
    float acc[4][16];
#pragma unroll
    for (int i = 0; i < 4; i++)
#pragma unroll
        for (int j = 0; j < 16; j++) acc[i][j] = 0.f;

    const int NKB = KIN / KT;   // 16
    // preload W1 tile 0  (16 x 256 = 1024 float4, 4 per thread)
#pragma unroll
    for (int q = 0; q < 4; q++) {
        int u = tid + q * 256;
        int r = u >> 6, c4 = u & 63;
        *(float4*)&Wsh[r * DHID + c4 * 4] =
            *(const float4*)(W1 + (size_t)r * DHID + c4 * 4);
    }
    __syncthreads();

    for (int kb = 0; kb < NKB; ++kb) {
        float* Wc = Wsh + (kb & 1) * KT * DHID;
        float* Wn = Wsh + ((kb + 1) & 1) * KT * DHID;
        float4 wreg[4];
        if (kb + 1 < NKB) {
#pragma unroll
            for (int q = 0; q < 4; q++) {
                int u = tid + q * 256;
                int r = u >> 6, c4 = u & 63;
                wreg[q] = *(const float4*)(W1 + (size_t)((kb + 1) * KT + r) * DHID + c4 * 4);
            }
        }
#pragma unroll
        for (int kk = 0; kk < KT; ++kk) {
            int k = kb * KT + kk;
            float a[4];
            *(float4*)a = *(const float4*)&At[k * TILE_M + ty * 4];
            float b[16];
#pragma unroll
            for (int j = 0; j < 16; j++) b[j] = Wc[kk * DHID + tx + 16 * j];
#pragma unroll
            for (int i = 0; i < 4; i++)
#pragma unroll
                for (int j = 0; j < 16; j++)
                    acc[i][j] = fmaf(a[i], b[j], acc[i][j]);
        }
        if (kb + 1 < NKB) {
#pragma unroll
            for (int q = 0; q < 4; q++) {
                int u = tid + q * 256;
                int r = u >> 6, c4 = u & 63;
                *(float4*)&Wn[r * DHID + c4 * 4] = wreg[q];
            }
        }
        __syncthreads();
    }

    // bias + silu -> H1t (transposed)
#pragma unroll
    for (int i = 0; i < 4; i++)
#pragma unroll
        for (int j = 0; j < 16; j++) {
            int col = tx + 16 * j;
            float v = acc[i][j] + __ldg(&b1[col]);
            v = v * (1.f / (1.f + __expf(-v)));
            H1t[col * TILE_M + ty * 4 + i] = v;
        }
    __syncthreads();

    // ---- GEMM2: H2 = H1 @ W2 + b2 --------------------------------------
    float acc2[4][8];
#pragma unroll
    for (int i = 0; i < 4; i++)
#pragma unroll
        for (int j = 0; j < 8; j++) acc2[i][j] = 0.f;

    // preload W2 tile 0 (16 x 128 = 512 float4, 2 per thread)
#pragma unroll
    for (int q = 0; q < 2; q++) {
        int u = tid + q * 256;
        int r = u >> 5, c4 = u & 31;
        *(float4*)&Wsh[r * DFEAT + c4 * 4] =
            *(const float4*)(W2 + (size_t)r * DFEAT + c4 * 4);
    }
    __syncthreads();

    for (int kb = 0; kb < NKB; ++kb) {   // DHID/KT = 16
        float* Wc = Wsh + (kb & 1) * KT * DFEAT;
        float* Wn = Wsh + ((kb + 1) & 1) * KT * DFEAT;
        float4 wreg[2];
        if (kb + 1 < NKB) {
#pragma unroll
            for (int q = 0; q < 2; q++) {
                int u = tid + q * 256;
                int r = u >> 5, c4 = u & 31;
                wreg[q] = *(const float4*)(W2 + (size_t)((kb + 1) * KT + r) * DFEAT + c4 * 4);
            }
        }
#pragma unroll
        for (int kk = 0; kk < KT; ++kk) {
            int k = kb * KT + kk;
            float a[4];
            *(float4*)a = *(const float4*)&H1t[k * TILE_M + ty * 4];
            float b[8];
#pragma unroll
            for (int j = 0; j < 8; j++) b[j] = Wc[kk * DFEAT + tx + 16 * j];
#pragma unroll
            for (int i = 0; i < 4; i++)
#pragma unroll
                for (int j = 0; j < 8; j++)
                    acc2[i][j] = fmaf(a[i], b[j], acc2[i][j]);
        }
        if (kb + 1 < NKB) {
#pragma unroll
            for (int q = 0; q < 2; q++) {
                int u = tid + q * 256;
                int r = u >> 5, c4 = u & 31;
                *(float4*)&Wn[r * DFEAT + c4 * 4] = wreg[q];
            }
        }
        __syncthreads();
    }

    // ---- bias + LayerNorm + residual + store ---------------------------
    float hv[4][8];
#pragma unroll
    for (int i = 0; i < 4; i++)
#pragma unroll
        for (int j = 0; j < 8; j++)
            hv[i][j] = acc2[i][j] + __ldg(&b2[tx + 16 * j]);

#pragma unroll
    for (int i = 0; i < 4; i++) {
        float s = 0.f, s2 = 0.f;
#pragma unroll
        for (int j = 0; j < 8; j++) { s += hv[i][j]; s2 += hv[i][j] * hv[i][j]; }
#pragma unroll
        for (int o = 8; o; o >>= 1) {
            s  += __shfl_xor_sync(0xffffffffu, s,  o, 16);
            s2 += __shfl_xor_sync(0xffffffffu, s2, o, 16);
        }
        float mu   = s * (1.f / 128.f);
        float var  = s2 * (1.f / 128.f) - mu * mu;
        float rstd = rsqrtf(var + 1e-5f);

        int row  = ty * 4 + i;
        int node = m0 + row;
        if (node < n) {
#pragma unroll
            for (int j = 0; j < 8; j++) {
                int col = tx + 16 * j;
                float o = (hv[i][j] - mu) * rstd * __ldg(&gamma[col])
                          + __ldg(&beta[col])
                          + At[col * TILE_M + row];      // residual x (col < 128)
                out[(size_t)node * DFEAT + col] = o;
            }
        }
    }
}

// ---------------------------------------------------------------------------
// Launch
// ---------------------------------------------------------------------------
extern "C" void kernel_launch(void* const* d_in, const int* in_sizes, int n_in,
                              void* d_out, int out_size)
{
    const float* x     = (const float*)d_in[0];
    const void*  ei    = d_in[1];
    const float* ea    = (const float*)d_in[2];
    const float* W1    = (const float*)d_in[3];
    const float* b1    = (const float*)d_in[4];
    const float* W2    = (const float*)d_in[5];
    const float* b2    = (const float*)d_in[6];
    const float* gamma = (const float*)d_in[7];
    const float* beta  = (const float*)d_in[8];
    float*       out   = (float*)d_out;

    int n = in_sizes[0] / DFEAT;      // 50000
    int E = in_sizes[2] / DFEAT;      // 1600000

    const int smem_bytes = (2 * KIN * TILE_M + 2 * KT * DHID) * (int)sizeof(float); // 160 KB
    cudaFuncSetAttribute(mlp_kernel, cudaFuncAttributeMaxDynamicSharedMemorySize,
                         smem_bytes);

    int n4 = n * (DFEAT / 4);
    detect_kernel<<<1, 256>>>((const int*)ei);
    zero_kernel<<<(n4 + 255) / 256, 256>>>(n4);
    scatter_kernel<<<(E + 7) / 8, 256>>>(ea, ei, E);
    mlp_kernel<<<(n + TILE_M - 1) / TILE_M, 256, smem_bytes>>>(
        x, W1, b1, W2, b2, gamma, beta, out, n);
}

// round 9
// speedup vs baseline: 1.1366x; 1.1366x over previous
#include <cuda_runtime.h>

// Problem constants (fixed by the dataset)
#define DFEAT   128     // node / edge feature dim
#define DHID    256     // hidden dim
#define KIN     256     // 2*DFEAT, GEMM1 K
#define TILE_M  64      // nodes per block in MLP kernel
#define KT      16      // K-tile depth
#define MAXN    50000

typedef unsigned long long ull;

// Scratch: aggregated edge features per node. 50000*128*4 = 25.6 MB.
__device__ __align__(16) float g_agg[(size_t)MAXN * DFEAT];
__device__ int g_is64;   // 1 if edge_index is int64 on device, 0 if int32

// XOR swizzle on the m (row) index of At/H1t, keyed by k. Granule 4 rows so
// LDS.128 row loads stay aligned; spreads stores across 4 bank groups.
#define SW(k) ((((k) >> 1) & 7) << 2)

// ---------------------------------------------------------------------------
// packed fp32x2 helpers (sm_100+)
// ---------------------------------------------------------------------------
__device__ __forceinline__ ull pack2(float x, float y)
{
    ull r; asm("mov.b64 %0, {%1, %2};" : "=l"(r) : "f"(x), "f"(y)); return r;
}
__device__ __forceinline__ void unpack2(ull v, float& x, float& y)
{
    asm("mov.b64 {%0, %1}, %2;" : "=f"(x), "=f"(y) : "l"(v));
}
__device__ __forceinline__ ull fma2(ull a, ull b, ull c)
{
    asm("fma.rn.f32x2 %0, %1, %2, %0;" : "+l"(c) : "l"(a), "l"(b));
    return c;
}

// ---------------------------------------------------------------------------
// Kernel 0: detect edge_index dtype (int64 vs int32), see R2 notes.
// ---------------------------------------------------------------------------
__global__ void detect_kernel(const int* __restrict__ ei32)
{
    __shared__ int s_ok;
    if (threadIdx.x == 0) s_ok = 1;
    __syncthreads();
    int bad = 0;
    for (int i = threadIdx.x; i < 1024; i += 256)
        if (ei32[2 * i + 1] != 0) bad = 1;
    if (bad) atomicAnd(&s_ok, 0);
    __syncthreads();
    if (threadIdx.x == 0) g_is64 = s_ok;
}

// ---------------------------------------------------------------------------
// Kernel 1: zero the aggregation buffer
// ---------------------------------------------------------------------------
__global__ void zero_kernel(int n4)
{
    int i = blockIdx.x * blockDim.x + threadIdx.x;
    if (i < n4) ((float4*)g_agg)[i] = make_float4(0.f, 0.f, 0.f, 0.f);
}

// ---------------------------------------------------------------------------
// Kernel 2: scatter-add edge features (one warp/edge, red.global.add.v4.f32)
// ---------------------------------------------------------------------------
__global__ void scatter_kernel(const float* __restrict__ edge_attr,
                               const void* __restrict__ edge_index,
                               int E)
{
    int w    = (blockIdx.x * blockDim.x + threadIdx.x) >> 5;
    int lane = threadIdx.x & 31;
    if (w >= E) return;

    int dst;
    if (g_is64)
        dst = (int)((const long long*)edge_index)[(size_t)E + w];  // row 1
    else
        dst = ((const int*)edge_index)[(size_t)E + w];
    dst = min(max(dst, 0), MAXN - 1);   // identity on valid data

    float4 v = ((const float4*)edge_attr)[(size_t)w * 32 + lane];
    float* p = g_agg + (size_t)dst * DFEAT + lane * 4;
    asm volatile("red.global.add.v4.f32 [%0], {%1, %2, %3, %4};"
                 :: "l"(p), "f"(v.x), "f"(v.y), "f"(v.z), "f"(v.w)
                 : "memory");
}

// ---------------------------------------------------------------------------
// Kernel 3: fused MLP + LayerNorm + residual, packed f32x2 math.
// Block = 256 threads (tx=tid&15, ty=tid>>4), TILE_M = 64 nodes.
//   At  [k][m^sw]  = [x | agg] transposed (swizzled rows)
//   H1t [k][m^sw]  = silu(A@W1+b1) transposed
// Thread (ty,tx): GEMM1 rows ty*4..+4, cols 4tx+64q (+0..3), q<4 -> 32 ull acc
//                 GEMM2 same rows,    cols 4tx+64q (+0..3), q<2 -> 16 ull acc
// W tiles double-buffered in smem; B loaded as ulonglong2 (pre-paired).
// ---------------------------------------------------------------------------
__global__ __launch_bounds__(256, 1)
void mlp_kernel(const float* __restrict__ x,
                const float* __restrict__ W1, const float* __restrict__ b1,
                const float* __restrict__ W2, const float* __restrict__ b2,
                const float* __restrict__ gamma, const float* __restrict__ beta,
                float* __restrict__ out, int n)
{
    extern __shared__ float sm[];
    float* At  = sm;                        // [KIN][TILE_M]   = 16384 f
    float* H1t = sm + KIN * TILE_M;         // [DHID][TILE_M]  = 16384 f
    float* Wsh = sm + 2 * KIN * TILE_M;     // 2 x [KT][DHID]  =  8192 f

    const int tid = threadIdx.x;
    const int tx  = tid & 15;
    const int ty  = tid >> 4;
    const int ty4 = ty * 4;
    const int m0  = blockIdx.x * TILE_M;

    // ---- stage A = [x | agg] transposed + swizzled ---------------------
    for (int u = tid; u < TILE_M * (KIN / 4); u += 256) {
        int m  = u >> 6;            // node row within tile
        int c4 = u & 63;
        int k  = c4 * 4;
        int node = m0 + m;
        float4 v = make_float4(0.f, 0.f, 0.f, 0.f);
        if (node < n) {
            const float* src = (k < DFEAT)
                ? (x     + (size_t)node * DFEAT + k)
                : (g_agg + (size_t)node * DFEAT + (k - DFEAT));
            v = *(const float4*)src;
        }
        At[(k + 0) * TILE_M + (m ^ SW(k + 0))] = v.x;
        At[(k + 1) * TILE_M + (m ^ SW(k + 1))] = v.y;
        At[(k + 2) * TILE_M + (m ^ SW(k + 2))] = v.z;
        At[(k + 3) * TILE_M + (m ^ SW(k + 3))] = v.w;
    }
    __syncthreads();

    // ---- GEMM1: H1 = silu(A @ W1 + b1) ---------------------------------
    ull acc[4][8];
#pragma unroll
    for (int i = 0; i < 4; i++)
#pragma unroll
        for (int j = 0; j < 8; j++) acc[i][j] = 0ull;

    const int NKB = KIN / KT;   // 16
    // preload W1 tile 0  (16 x 256 = 1024 float4, 4 per thread)
#pragma unroll
    for (int q = 0; q < 4; q++) {
        int u = tid + q * 256;
        int r = u >> 6, c4 = u & 63;
        *(float4*)&Wsh[r * DHID + c4 * 4] =
            *(const float4*)(W1 + (size_t)r * DHID + c4 * 4);
    }
    __syncthreads();

    for (int kb = 0; kb < NKB; ++kb) {
        const float* Wc = Wsh + (kb & 1) * KT * DHID;
        float*       Wn = Wsh + ((kb + 1) & 1) * KT * DHID;
        float4 wreg[4];
        if (kb + 1 < NKB) {
#pragma unroll
            for (int q = 0; q < 4; q++) {
                int u = tid + q * 256;
                int r = u >> 6, c4 = u & 63;
                wreg[q] = *(const float4*)(W1 + (size_t)((kb + 1) * KT + r) * DHID + c4 * 4);
            }
        }
#pragma unroll 8
        for (int kk = 0; kk < KT; ++kk) {
            int k = kb * KT + kk;
            // SW(k) == SW(kk) here (kb*16 contributes 0 mod 8 after >>1)
            float4 a4 = *(const float4*)&At[k * TILE_M + (ty4 ^ SW(kk))];
            ull ad[4] = { pack2(a4.x, a4.x), pack2(a4.y, a4.y),
                          pack2(a4.z, a4.z), pack2(a4.w, a4.w) };
#pragma unroll
            for (int q = 0; q < 4; q++) {
                ulonglong2 bv = *(const ulonglong2*)(Wc + kk * DHID + 4 * tx + 64 * q);
#pragma unroll
                for (int i = 0; i < 4; i++) {
                    acc[i][2 * q]     = fma2(ad[i], bv.x, acc[i][2 * q]);
                    acc[i][2 * q + 1] = fma2(ad[i], bv.y, acc[i][2 * q + 1]);
                }
            }
        }
        if (kb + 1 < NKB) {
#pragma unroll
            for (int q = 0; q < 4; q++) {
                int u = tid + q * 256;
                int r = u >> 6, c4 = u & 63;
                *(float4*)&Wn[r * DHID + c4 * 4] = wreg[q];
            }
        }
        __syncthreads();
    }

    // bias + silu -> H1t (transposed + swizzled)
#pragma unroll
    for (int q = 0; q < 4; q++) {
        float4 bb = __ldg((const float4*)&b1[4 * tx + 64 * q]);
#pragma unroll
        for (int i = 0; i < 4; i++) {
            float v0, v1, v2, v3;
            unpack2(acc[i][2 * q],     v0, v1);
            unpack2(acc[i][2 * q + 1], v2, v3);
            v0 += bb.x; v1 += bb.y; v2 += bb.z; v3 += bb.w;
            v0 = v0 * (1.f / (1.f + __expf(-v0)));
            v1 = v1 * (1.f / (1.f + __expf(-v1)));
            v2 = v2 * (1.f / (1.f + __expf(-v2)));
            v3 = v3 * (1.f / (1.f + __expf(-v3)));
            int col = 4 * tx + 64 * q;
            int row = ty4 + i;
            H1t[(col + 0) * TILE_M + (row ^ SW(col + 0))] = v0;
            H1t[(col + 1) * TILE_M + (row ^ SW(col + 1))] = v1;
            H1t[(col + 2) * TILE_M + (row ^ SW(col + 2))] = v2;
            H1t[(col + 3) * TILE_M + (row ^ SW(col + 3))] = v3;
        }
    }
    __syncthreads();

    // ---- GEMM2: H2 = H1 @ W2 + b2 --------------------------------------
    ull acc2[4][4];
#pragma unroll
    for (int i = 0; i < 4; i++)
#pragma unroll
        for (int j = 0; j < 4; j++) acc2[i][j] = 0ull;

    // preload W2 tile 0 (16 x 128 = 512 float4, 2 per thread)
#pragma unroll
    for (int q = 0; q < 2; q++) {
        int u = tid + q * 256;
        int r = u >> 5, c4 = u & 31;
        *(float4*)&Wsh[r * DFEAT + c4 * 4] =
            *(const float4*)(W2 + (size_t)r * DFEAT + c4 * 4);
    }
    __syncthreads();

    for (int kb = 0; kb < NKB; ++kb) {   // DHID/KT = 16
        const float* Wc = Wsh + (kb & 1) * KT * DFEAT;
        float*       Wn = Wsh + ((kb + 1) & 1) * KT * DFEAT;
        float4 wreg[2];
        if (kb + 1 < NKB) {
#pragma unroll
            for (int q = 0; q < 2; q++) {
                int u = tid + q * 256;
                int r = u >> 5, c4 = u & 31;
                wreg[q] = *(const float4*)(W2 + (size_t)((kb + 1) * KT + r) * DFEAT + c4 * 4);
            }
        }
#pragma unroll 8
        for (int kk = 0; kk < KT; ++kk) {
            int k = kb * KT + kk;
            float4 a4 = *(const float4*)&H1t[k * TILE_M + (ty4 ^ SW(kk))];
            ull ad[4] = { pack2(a4.x, a4.x), pack2(a4.y, a4.y),
                          pack2(a4.z, a4.z), pack2(a4.w, a4.w) };
#pragma unroll
            for (int q = 0; q < 2; q++) {
                ulonglong2 bv = *(const ulonglong2*)(Wc + kk * DFEAT + 4 * tx + 64 * q);
#pragma unroll
                for (int i = 0; i < 4; i++) {
                    acc2[i][2 * q]     = fma2(ad[i], bv.x, acc2[i][2 * q]);
                    acc2[i][2 * q + 1] = fma2(ad[i], bv.y, acc2[i][2 * q + 1]);
                }
            }
        }
        if (kb + 1 < NKB) {
#pragma unroll
            for (int q = 0; q < 2; q++) {
                int u = tid + q * 256;
                int r = u >> 5, c4 = u & 31;
                *(float4*)&Wn[r * DFEAT + c4 * 4] = wreg[q];
            }
        }
        __syncthreads();
    }

    // ---- bias + LayerNorm + residual + store ---------------------------
    float hv[4][8];     // [row i][j] with col = 4tx + 64*(j>>2) + (j&3)
#pragma unroll
    for (int q = 0; q < 2; q++) {
        float4 bb = __ldg((const float4*)&b2[4 * tx + 64 * q]);
#pragma unroll
        for (int i = 0; i < 4; i++) {
            float v0, v1, v2, v3;
            unpack2(acc2[i][2 * q],     v0, v1);
            unpack2(acc2[i][2 * q + 1], v2, v3);
            hv[i][4 * q + 0] = v0 + bb.x;
            hv[i][4 * q + 1] = v1 + bb.y;
            hv[i][4 * q + 2] = v2 + bb.z;
            hv[i][4 * q + 3] = v3 + bb.w;
        }
    }

    float4 gm[2], bt[2];
#pragma unroll
    for (int q = 0; q < 2; q++) {
        gm[q] = __ldg((const float4*)&gamma[4 * tx + 64 * q]);
        bt[q] = __ldg((const float4*)&beta [4 * tx + 64 * q]);
    }

#pragma unroll
    for (int i = 0; i < 4; i++) {
        float s = 0.f, s2 = 0.f;
#pragma unroll
        for (int j = 0; j < 8; j++) { s += hv[i][j]; s2 += hv[i][j] * hv[i][j]; }
#pragma unroll
        for (int o = 8; o; o >>= 1) {
            s  += __shfl_xor_sync(0xffffffffu, s,  o, 16);
            s2 += __shfl_xor_sync(0xffffffffu, s2, o, 16);
        }
        float mu   = s * (1.f / 128.f);
        float var  = s2 * (1.f / 128.f) - mu * mu;
        float rstd = rsqrtf(var + 1e-5f);

        int row  = ty4 + i;
        int node = m0 + row;
        if (node < n) {
#pragma unroll
            for (int q = 0; q < 2; q++) {
                int col = 4 * tx + 64 * q;
                const float* g4 = (const float*)&gm[q];
                const float* be4 = (const float*)&bt[q];
                float4 o4;
                float* op = (float*)&o4;
#pragma unroll
                for (int e = 0; e < 4; e++) {
                    float rx = At[(col + e) * TILE_M + (row ^ SW(col + e))];
                    op[e] = (hv[i][4 * q + e] - mu) * rstd * g4[e] + be4[e] + rx;
                }
                *(float4*)&out[(size_t)node * DFEAT + col] = o4;
            }
        }
    }
}

// ---------------------------------------------------------------------------
// Launch
// ---------------------------------------------------------------------------
extern "C" void kernel_launch(void* const* d_in, const int* in_sizes, int n_in,
                              void* d_out, int out_size)
{
    const float* x     = (const float*)d_in[0];
    const void*  ei    = d_in[1];
    const float* ea    = (const float*)d_in[2];
    const float* W1    = (const float*)d_in[3];
    const float* b1    = (const float*)d_in[4];
    const float* W2    = (const float*)d_in[5];
    const float* b2    = (const float*)d_in[6];
    const float* gamma = (const float*)d_in[7];
    const float* beta  = (const float*)d_in[8];
    float*       out   = (float*)d_out;

    int n = in_sizes[0] / DFEAT;      // 50000
    int E = in_sizes[2] / DFEAT;      // 1600000

    const int smem_bytes = (2 * KIN * TILE_M + 2 * KT * DHID) * (int)sizeof(float); // 160 KB
    cudaFuncSetAttribute(mlp_kernel, cudaFuncAttributeMaxDynamicSharedMemorySize,
                         smem_bytes);

    int n4 = n * (DFEAT / 4);
    detect_kernel<<<1, 256>>>((const int*)ei);
    zero_kernel<<<(n4 + 255) / 256, 256>>>(n4);
    scatter_kernel<<<(E + 7) / 8, 256>>>(ea, ei, E);
    mlp_kernel<<<(n + TILE_M - 1) / TILE_M, 256, smem_bytes>>>(
        x, W1, b1, W2, b2, gamma, beta, out, n);
}